// round 7
// baseline (speedup 1.0000x reference)
#include <cuda_runtime.h>
#include <math.h>
#include <stdint.h>

#define T_STEPS 12
#define HID     1024
#define B_SZ    2048
#define IMG     512
#define NCLS    51
#define MROWS   (T_STEPS * B_SZ)   /* 24576; row r = b*T + t */

#define SCALE_X 1.7320508075688772f  /* sqrt(1 + 2*e^0) = sqrt(3) */

// ---------------- scratch (device globals; no allocations allowed) ----------
__device__ float g_U [(size_t)MROWS * 4096];   // GEMM outputs (max width 4096)
__device__ float g_h0[(size_t)MROWS * HID];
__device__ float g_h1[(size_t)MROWS * HID];
__device__ float g_hbar[(size_t)B_SZ * HID];

// ---------------- SGEMM: C[M,N] = A[M,K] * B[K,N], all row-major ------------
// 128x128 block tile, BK=16, 256 threads, 8x8 per-thread microtile.
// Requires M%128==0, N%128==0, K%16==0 (true for all 3 big GEMMs).
__global__ void __launch_bounds__(256)
sgemm128(const float* __restrict__ A, const float* __restrict__ Bm,
         float* __restrict__ C, int M, int N, int K)
{
    __shared__ float As[16][132];   // transposed A tile (+pad)
    __shared__ float Bs[16][132];   // B tile (+pad)

    const int tid  = threadIdx.x;
    const int row0 = blockIdx.y * 128;
    const int col0 = blockIdx.x * 128;
    const int tx   = tid & 15;       // 0..15 -> cols tx*8..+7
    const int ty   = tid >> 4;       // 0..15 -> rows ty*8..+7

    // load mappings (2x float4 for A, 2x float4 for B per thread)
    const int a_r = tid >> 2;            // 0..63
    const int a_c = (tid & 3) << 2;      // 0,4,8,12
    const int b_r = tid >> 5;            // 0..7
    const int b_c = (tid & 31) << 2;     // 0..124

    const float* Ap  = A + (size_t)(row0 + a_r) * K + a_c;
    const float* Ap2 = Ap + (size_t)64 * K;
    const float* Bp  = Bm + (size_t)b_r * N + col0 + b_c;

    float acc[8][8];
    #pragma unroll
    for (int i = 0; i < 8; ++i)
        #pragma unroll
        for (int j = 0; j < 8; ++j) acc[i][j] = 0.0f;

    for (int k0 = 0; k0 < K; k0 += 16) {
        float4 a0 = *(const float4*)(Ap  + k0);
        float4 a1 = *(const float4*)(Ap2 + k0);
        float4 b0 = *(const float4*)(Bp + (size_t)k0 * N);
        float4 b1 = *(const float4*)(Bp + (size_t)(k0 + 8) * N);

        As[a_c + 0][a_r] = a0.x;  As[a_c + 1][a_r] = a0.y;
        As[a_c + 2][a_r] = a0.z;  As[a_c + 3][a_r] = a0.w;
        As[a_c + 0][a_r + 64] = a1.x;  As[a_c + 1][a_r + 64] = a1.y;
        As[a_c + 2][a_r + 64] = a1.z;  As[a_c + 3][a_r + 64] = a1.w;
        *(float4*)&Bs[b_r    ][b_c] = b0;
        *(float4*)&Bs[b_r + 8][b_c] = b1;
        __syncthreads();

        #pragma unroll
        for (int kk = 0; kk < 16; ++kk) {
            float ra[8], rb[8];
            *(float4*)&ra[0] = *(const float4*)&As[kk][ty * 8];
            *(float4*)&ra[4] = *(const float4*)&As[kk][ty * 8 + 4];
            *(float4*)&rb[0] = *(const float4*)&Bs[kk][tx * 8];
            *(float4*)&rb[4] = *(const float4*)&Bs[kk][tx * 8 + 4];
            #pragma unroll
            for (int i = 0; i < 8; ++i)
                #pragma unroll
                for (int j = 0; j < 8; ++j)
                    acc[i][j] = fmaf(ra[i], rb[j], acc[i][j]);
        }
        __syncthreads();
    }

    #pragma unroll
    for (int i = 0; i < 8; ++i) {
        float* Cp = C + (size_t)(row0 + ty * 8 + i) * N + col0 + tx * 8;
        float4 v0 = make_float4(acc[i][0], acc[i][1], acc[i][2], acc[i][3]);
        float4 v1 = make_float4(acc[i][4], acc[i][5], acc[i][6], acc[i][7]);
        *(float4*)Cp       = v0;
        *((float4*)Cp + 1) = v1;
    }
}

// ---------------- SRU recurrence --------------------------------------------
// One thread per (b, d). Layout: U rows r = b*T+t (stride `ustride` floats),
// chunks u0/u1/u2 at columns 0/HID/2*HID, residual at 3*HID (layer 0) or from
// the layer input h (layers 1,2).
__device__ __forceinline__ float sigmoidf_(float x) {
    return 1.0f / (1.0f + expf(-x));
}

template <bool RESID_FROM_U>
__global__ void __launch_bounds__(HID)
sru_layer_kernel(const float* __restrict__ U, int ustride,
                 const float* __restrict__ resid_h,
                 const float* __restrict__ vc, const float* __restrict__ bias,
                 float* __restrict__ h_out)
{
    const int d = threadIdx.x;
    const int b = blockIdx.x;

    const float vf = vc[d],      vr = vc[HID + d];
    const float bf = bias[d],    br = bias[HID + d];

    const float* Ub = U + (size_t)b * T_STEPS * ustride;
    const float* rb = RESID_FROM_U ? nullptr : (resid_h + (size_t)b * T_STEPS * HID);
    float* hb = h_out + (size_t)b * T_STEPS * HID;

    float c = 0.0f;
    #pragma unroll
    for (int t = 0; t < T_STEPS; ++t) {
        const float* Ut = Ub + (size_t)t * ustride;
        const float u0 = Ut[d];
        const float u1 = Ut[HID + d];
        const float u2 = Ut[2 * HID + d];
        const float xt = RESID_FROM_U ? Ut[3 * HID + d] : rb[(size_t)t * HID + d];

        const float f = sigmoidf_(u1 + vf * c + bf);
        c = f * c + (1.0f - f) * u0;
        const float r = sigmoidf_(u2 + vr * c + br);
        hb[(size_t)t * HID + d] = r * tanhf(c) + (1.0f - r) * xt * SCALE_X;
    }
}

// ---------------- mean over t ------------------------------------------------
__global__ void mean_kernel(const float* __restrict__ h, float* __restrict__ hbar)
{
    const int idx = blockIdx.x * blockDim.x + threadIdx.x;  // B*HID threads
    const int b = idx / HID;
    const int d = idx - b * HID;
    const float* hb = h + (size_t)b * T_STEPS * HID + d;
    float s = 0.0f;
    #pragma unroll
    for (int t = 0; t < T_STEPS; ++t) s += hb[(size_t)t * HID];
    hbar[idx] = s * (1.0f / T_STEPS);
}

// ---------------- FC head: out[b,c] = hbar[b,:] @ fc_w[:,c] + fc_b[c] --------
__global__ void __launch_bounds__(256)
fc_kernel(const float* __restrict__ hbar, const float* __restrict__ w,
          const float* __restrict__ bias, float* __restrict__ out)
{
    __shared__ float hrow[HID];
    __shared__ float part[4][64];
    const int b   = blockIdx.x;
    const int tid = threadIdx.x;

    #pragma unroll
    for (int i = tid; i < HID; i += 256) hrow[i] = hbar[(size_t)b * HID + i];
    __syncthreads();

    const int c  = tid & 63;
    const int sl = tid >> 6;     // 4 K-slices of 256
    float s = 0.0f;
    if (c < NCLS) {
        const int d0 = sl * 256;
        #pragma unroll 8
        for (int d = d0; d < d0 + 256; ++d)
            s = fmaf(hrow[d], w[(size_t)d * NCLS + c], s);
    }
    part[sl][c] = s;
    __syncthreads();

    if (tid < NCLS)
        out[(size_t)b * NCLS + tid] =
            part[0][tid] + part[1][tid] + part[2][tid] + part[3][tid] + bias[tid];
}

// ---------------- launch -----------------------------------------------------
extern "C" void kernel_launch(void* const* d_in, const int* in_sizes, int n_in,
                              void* d_out, int out_size)
{
    const float* x    = (const float*)d_in[0];
    const float* W0   = (const float*)d_in[1];
    const float* W1   = (const float*)d_in[2];
    const float* W2   = (const float*)d_in[3];
    const float* vc0  = (const float*)d_in[4];
    const float* vc1  = (const float*)d_in[5];
    const float* vc2  = (const float*)d_in[6];
    const float* b0   = (const float*)d_in[7];
    const float* b1   = (const float*)d_in[8];
    const float* b2   = (const float*)d_in[9];
    const float* fcw  = (const float*)d_in[10];
    const float* fcb  = (const float*)d_in[11];
    float* out = (float*)d_out;

    float *U, *h0, *h1, *hbar;
    cudaGetSymbolAddress((void**)&U,    g_U);
    cudaGetSymbolAddress((void**)&h0,   g_h0);
    cudaGetSymbolAddress((void**)&h1,   g_h1);
    cudaGetSymbolAddress((void**)&hbar, g_hbar);

    // Layer 0: U = x @ W0  (M=24576, N=4096, K=512); residual = U chunk 3
    sgemm128<<<dim3(4096 / 128, MROWS / 128), 256>>>(x, W0, U, MROWS, 4096, IMG);
    sru_layer_kernel<true><<<B_SZ, HID>>>(U, 4096, nullptr, vc0, b0, h0);

    // Layer 1: U = h0 @ W1 (N=3072, K=1024); residual = h0
    sgemm128<<<dim3(3072 / 128, MROWS / 128), 256>>>(h0, W1, U, MROWS, 3072, HID);
    sru_layer_kernel<false><<<B_SZ, HID>>>(U, 3072, h0, vc1, b1, h1);

    // Layer 2: U = h1 @ W2; residual = h1
    sgemm128<<<dim3(3072 / 128, MROWS / 128), 256>>>(h1, W2, U, MROWS, 3072, HID);
    sru_layer_kernel<false><<<B_SZ, HID>>>(U, 3072, h1, vc2, b2, h0);

    // mean over t, then FC (mean commutes with the linear head)
    mean_kernel<<<(B_SZ * HID) / 256, 256>>>(h0, hbar);
    fc_kernel<<<B_SZ, 256>>>(hbar, fcw, fcb, out);
}

// round 10
// speedup vs baseline: 2.6234x; 2.6234x over previous
#include <cuda_runtime.h>
#include <cuda_bf16.h>
#include <math.h>
#include <stdint.h>

#define T_STEPS 12
#define HID     1024
#define B_SZ    2048
#define IMG     512
#define NCLS    51
#define MROWS   (T_STEPS * B_SZ)   /* 24576; row r = b*T + t */

#define SCALE_X 1.7320508075688772f  /* sqrt(3) */

// ---------------- scratch (device globals; no allocations allowed) ----------
__device__ __align__(256) float g_U [(size_t)MROWS * 4096];
__device__ __align__(256) float g_h0[(size_t)MROWS * HID];
__device__ __align__(256) float g_h1[(size_t)MROWS * HID];
__device__ __align__(256) float g_hbar[(size_t)B_SZ * HID];
// bf16 hi/lo splits of activations
__device__ __align__(256) __nv_bfloat16 g_xh[(size_t)MROWS * IMG];
__device__ __align__(256) __nv_bfloat16 g_xl[(size_t)MROWS * IMG];
__device__ __align__(256) __nv_bfloat16 g_ah[(size_t)MROWS * HID];
__device__ __align__(256) __nv_bfloat16 g_al[(size_t)MROWS * HID];
__device__ __align__(256) __nv_bfloat16 g_bh[(size_t)MROWS * HID];
__device__ __align__(256) __nv_bfloat16 g_bl[(size_t)MROWS * HID];
// bf16 splits of transposed weights [N][K] (max 4096x1024)
__device__ __align__(256) __nv_bfloat16 g_wth[(size_t)4096 * 1024];
__device__ __align__(256) __nv_bfloat16 g_wtl[(size_t)4096 * 1024];

// ======================= arch-neutral PTX helpers ===========================
__device__ __forceinline__ uint32_t smem_u32(const void* p) {
    uint32_t a;
    asm("{ .reg .u64 t; cvta.to.shared.u64 t, %1; cvt.u32.u64 %0, t; }"
        : "=r"(a) : "l"(p));
    return a;
}
__device__ __forceinline__ void cpa16(uint32_t dst, const void* src) {
    asm volatile("cp.async.cg.shared.global [%0], [%1], 16;"
                 :: "r"(dst), "l"(src) : "memory");
}
__device__ __forceinline__ void cpa_commit() {
    asm volatile("cp.async.commit_group;" ::: "memory");
}
__device__ __forceinline__ void cpa_wait2() {
    asm volatile("cp.async.wait_group 2;" ::: "memory");
}
__device__ __forceinline__ void ldsm4(uint32_t& r0, uint32_t& r1,
                                      uint32_t& r2, uint32_t& r3, uint32_t addr) {
    asm volatile("ldmatrix.sync.aligned.m8n8.x4.shared.b16 {%0,%1,%2,%3}, [%4];"
                 : "=r"(r0), "=r"(r1), "=r"(r2), "=r"(r3) : "r"(addr));
}
__device__ __forceinline__ void mma_bf16(float* c, const uint32_t* a,
                                         const uint32_t* b) {
    asm volatile(
        "mma.sync.aligned.m16n8k16.row.col.f32.bf16.bf16.f32 "
        "{%0,%1,%2,%3}, {%4,%5,%6,%7}, {%8,%9}, {%0,%1,%2,%3};"
        : "+f"(c[0]), "+f"(c[1]), "+f"(c[2]), "+f"(c[3])
        : "r"(a[0]), "r"(a[1]), "r"(a[2]), "r"(a[3]), "r"(b[0]), "r"(b[1]));
}

// ======================= bf16x3 tensor-core GEMM ============================
// C[M,N] (fp32) = Ah*Bh + Ah*Bl + Al*Bh (bf16 in, fp32 accumulate).
// A: [M,K] row-major; B: [N,K] row-major (weights pre-transposed -> mma row.col).
// CTA tile 128x128, BK=64 (128B rows, SW128 XOR swizzle), 8 warps of 64x32,
// 3-stage cp.async pipeline. grid = (N/128, M/128), 256 threads.
#define STAGE_TILE  16384                   /* 128 rows x 128 B (one bf16 tile) */
#define STAGE_BYTES (4 * STAGE_TILE)        /* Ah, Al, Bh, Bl */
#define NSTAGE      3
#define SMEM_GEMM   (NSTAGE * STAGE_BYTES)  /* 196608 B */

__global__ void __launch_bounds__(256)
gemm_bf16x3(const __nv_bfloat16* __restrict__ Ah, const __nv_bfloat16* __restrict__ Al,
            const __nv_bfloat16* __restrict__ Bh, const __nv_bfloat16* __restrict__ Bl,
            float* __restrict__ C, int K, int Nld)
{
    extern __shared__ char smem[];
    const uint32_t sb = smem_u32(smem);
    const int tid  = threadIdx.x;
    const int lane = tid & 31;
    const int wid  = tid >> 5;
    const int row0 = blockIdx.y * 128;
    const int col0 = blockIdx.x * 128;
    const int wm   = (wid >> 2) * 64;   // warp M offset (0 / 64)
    const int wn   = (wid & 3) * 32;    // warp N offset (0..96)

    const int NC = K >> 6;              // K/64 chunks

    float acc[4][4][4];
    #pragma unroll
    for (int i = 0; i < 4; ++i)
        #pragma unroll
        for (int j = 0; j < 4; ++j)
            #pragma unroll
            for (int q = 0; q < 4; ++q) acc[i][j][q] = 0.0f;

    // ---- stage fill: 4 tiles x 1024 16B-chunks, 256 threads -> 16 cp.async each
    auto fill = [&](int ck) {
        const int k0 = ck << 6;
        const uint32_t stg = sb + (uint32_t)(ck % NSTAGE) * STAGE_BYTES;
        #pragma unroll
        for (int i = 0; i < 4; ++i) {
            const int lin = tid + i * 256;     // 0..1023
            const int r   = lin >> 3;          // row 0..127
            const int c   = lin & 7;           // 16B chunk 0..7
            const uint32_t so = (uint32_t)(r * 128 + ((c ^ (r & 7)) << 4));
            const size_t ao = (size_t)(row0 + r) * K + k0 + c * 8;
            const size_t bo = (size_t)(col0 + r) * K + k0 + c * 8;
            cpa16(stg + 0 * STAGE_TILE + so, Ah + ao);
            cpa16(stg + 1 * STAGE_TILE + so, Al + ao);
            cpa16(stg + 2 * STAGE_TILE + so, Bh + bo);
            cpa16(stg + 3 * STAGE_TILE + so, Bl + bo);
        }
    };

    fill(0); cpa_commit();
    if (NC > 1) fill(1);
    cpa_commit();

    // lane-constant ldmatrix address components
    const int arow  = wm + (lane & 15);                 // A: row within tile
    const int achi  = lane >> 4;                        // A: k-chunk hi bit
    const int brow  = (lane & 7) + 8 * (lane >> 4);     // B: row within 16-col group
    const int bchi  = (lane >> 3) & 1;                  // B: k-chunk hi bit

    for (int ck = 0; ck < NC; ++ck) {
        if (ck + 2 < NC) fill(ck + 2);
        cpa_commit();                       // uniform group count (may be empty)
        cpa_wait2();                        // group for chunk ck complete
        __syncthreads();

        const uint32_t stg = sb + (uint32_t)(ck % NSTAGE) * STAGE_BYTES;
        const uint32_t sAh = stg, sAl = stg + STAGE_TILE;
        const uint32_t sBh = stg + 2 * STAGE_TILE, sBl = stg + 3 * STAGE_TILE;

        #pragma unroll
        for (int ks = 0; ks < 4; ++ks) {    // 4 x k16 per 64-chunk
            uint32_t fah[4][4], fal[4][4], fbh[4][2], fbl[4][2];
            #pragma unroll
            for (int mt = 0; mt < 4; ++mt) {
                const int r = arow + mt * 16;
                const int c = ks * 2 + achi;
                const uint32_t off = (uint32_t)(r * 128 + ((c ^ (r & 7)) << 4));
                ldsm4(fah[mt][0], fah[mt][1], fah[mt][2], fah[mt][3], sAh + off);
                ldsm4(fal[mt][0], fal[mt][1], fal[mt][2], fal[mt][3], sAl + off);
            }
            #pragma unroll
            for (int nb2 = 0; nb2 < 2; ++nb2) {
                const int r = wn + nb2 * 16 + brow;
                const int c = ks * 2 + bchi;
                const uint32_t off = (uint32_t)(r * 128 + ((c ^ (r & 7)) << 4));
                uint32_t q0, q1, q2, q3;
                ldsm4(q0, q1, q2, q3, sBh + off);
                fbh[nb2 * 2][0] = q0; fbh[nb2 * 2][1] = q1;
                fbh[nb2 * 2 + 1][0] = q2; fbh[nb2 * 2 + 1][1] = q3;
                ldsm4(q0, q1, q2, q3, sBl + off);
                fbl[nb2 * 2][0] = q0; fbl[nb2 * 2][1] = q1;
                fbl[nb2 * 2 + 1][0] = q2; fbl[nb2 * 2 + 1][1] = q3;
            }
            #pragma unroll
            for (int mt = 0; mt < 4; ++mt)
                #pragma unroll
                for (int nb = 0; nb < 4; ++nb) {
                    mma_bf16(acc[mt][nb], fah[mt], fbh[nb]);
                    mma_bf16(acc[mt][nb], fah[mt], fbl[nb]);
                    mma_bf16(acc[mt][nb], fal[mt], fbh[nb]);
                }
        }
        __syncthreads();                    // stage free before refill
    }

    // ---- epilogue: direct fp32 stores (frag: rows g,g+8; cols 2i,2i+1)
    const int g  = lane >> 2;
    const int i2 = (lane & 3) * 2;
    #pragma unroll
    for (int mt = 0; mt < 4; ++mt) {
        #pragma unroll
        for (int nb = 0; nb < 4; ++nb) {
            const int row = row0 + wm + mt * 16 + g;
            const int col = col0 + wn + nb * 8 + i2;
            float* p  = C + (size_t)row * Nld + col;
            float* p2 = C + (size_t)(row + 8) * Nld + col;
            *(float2*)p  = make_float2(acc[mt][nb][0], acc[mt][nb][1]);
            *(float2*)p2 = make_float2(acc[mt][nb][2], acc[mt][nb][3]);
        }
    }
}

// ---------------- fp32 -> bf16 hi/lo split ----------------------------------
__global__ void split_f32(const float* __restrict__ a,
                          __nv_bfloat16* __restrict__ hi,
                          __nv_bfloat16* __restrict__ lo)
{
    const int i = blockIdx.x * blockDim.x + threadIdx.x;
    const float v = a[i];
    const __nv_bfloat16 h = __float2bfloat16(v);
    hi[i] = h;
    lo[i] = __float2bfloat16(v - __bfloat162float(h));
}

// ---------------- weight transpose + split: W[K,N] -> Wt_{h,l}[N,K] ---------
__global__ void __launch_bounds__(256)
wsplit_t(const float* __restrict__ W, int K, int N,
         __nv_bfloat16* __restrict__ Th, __nv_bfloat16* __restrict__ Tl)
{
    __shared__ float tile[32][33];
    const int n0 = blockIdx.x * 32, k0 = blockIdx.y * 32;
    const int tx = threadIdx.x, ty = threadIdx.y;   // (32, 8)
    #pragma unroll
    for (int r = 0; r < 4; ++r)
        tile[ty + 8 * r][tx] = W[(size_t)(k0 + ty + 8 * r) * N + n0 + tx];
    __syncthreads();
    #pragma unroll
    for (int r = 0; r < 4; ++r) {
        const int n = n0 + ty + 8 * r, k = k0 + tx;
        const float v = tile[tx][ty + 8 * r];
        const __nv_bfloat16 h = __float2bfloat16(v);
        Th[(size_t)n * K + k] = h;
        Tl[(size_t)n * K + k] = __float2bfloat16(v - __bfloat162float(h));
    }
}

// ---------------- SRU recurrence (optionally emits bf16 split of h) ---------
__device__ __forceinline__ float sigmoidf_(float x) {
    return 1.0f / (1.0f + expf(-x));
}

template <bool RESID_FROM_U, bool WRITE_SPLIT>
__global__ void __launch_bounds__(HID)
sru_layer_kernel(const float* __restrict__ U, int ustride,
                 const float* __restrict__ resid_h,
                 const float* __restrict__ vc, const float* __restrict__ bias,
                 float* __restrict__ h_out,
                 __nv_bfloat16* __restrict__ hh, __nv_bfloat16* __restrict__ hl)
{
    const int d = threadIdx.x;
    const int b = blockIdx.x;

    const float vf = vc[d],   vr = vc[HID + d];
    const float bf = bias[d], br = bias[HID + d];

    const float* Ub = U + (size_t)b * T_STEPS * ustride;
    const float* rb = RESID_FROM_U ? nullptr : (resid_h + (size_t)b * T_STEPS * HID);
    const size_t ob = (size_t)b * T_STEPS * HID;

    float c = 0.0f;
    #pragma unroll
    for (int t = 0; t < T_STEPS; ++t) {
        const float* Ut = Ub + (size_t)t * ustride;
        const float u0 = Ut[d];
        const float u1 = Ut[HID + d];
        const float u2 = Ut[2 * HID + d];
        const float xt = RESID_FROM_U ? Ut[3 * HID + d] : rb[(size_t)t * HID + d];

        const float f = sigmoidf_(u1 + vf * c + bf);
        c = f * c + (1.0f - f) * u0;
        const float r = sigmoidf_(u2 + vr * c + br);
        const float h = r * tanhf(c) + (1.0f - r) * xt * SCALE_X;
        const size_t o = ob + (size_t)t * HID + d;
        h_out[o] = h;
        if (WRITE_SPLIT) {
            const __nv_bfloat16 hi = __float2bfloat16(h);
            hh[o] = hi;
            hl[o] = __float2bfloat16(h - __bfloat162float(hi));
        }
    }
}

// ---------------- mean over t ------------------------------------------------
__global__ void mean_kernel(const float* __restrict__ h, float* __restrict__ hbar)
{
    const int idx = blockIdx.x * blockDim.x + threadIdx.x;
    const int b = idx / HID;
    const int d = idx - b * HID;
    const float* hb = h + (size_t)b * T_STEPS * HID + d;
    float s = 0.0f;
    #pragma unroll
    for (int t = 0; t < T_STEPS; ++t) s += hb[(size_t)t * HID];
    hbar[idx] = s * (1.0f / T_STEPS);
}

// ---------------- FC head ----------------------------------------------------
__global__ void __launch_bounds__(256)
fc_kernel(const float* __restrict__ hbar, const float* __restrict__ w,
          const float* __restrict__ bias, float* __restrict__ out)
{
    __shared__ float hrow[HID];
    __shared__ float part[4][64];
    const int b   = blockIdx.x;
    const int tid = threadIdx.x;

    #pragma unroll
    for (int i = tid; i < HID; i += 256) hrow[i] = hbar[(size_t)b * HID + i];
    __syncthreads();

    const int c  = tid & 63;
    const int sl = tid >> 6;
    float s = 0.0f;
    if (c < NCLS) {
        const int d0 = sl * 256;
        #pragma unroll 8
        for (int d = d0; d < d0 + 256; ++d)
            s = fmaf(hrow[d], w[(size_t)d * NCLS + c], s);
    }
    part[sl][c] = s;
    __syncthreads();

    if (tid < NCLS)
        out[(size_t)b * NCLS + tid] =
            part[0][tid] + part[1][tid] + part[2][tid] + part[3][tid] + bias[tid];
}

// ---------------- launch -----------------------------------------------------
extern "C" void kernel_launch(void* const* d_in, const int* in_sizes, int n_in,
                              void* d_out, int out_size)
{
    const float* x    = (const float*)d_in[0];
    const float* W0   = (const float*)d_in[1];
    const float* W1   = (const float*)d_in[2];
    const float* W2   = (const float*)d_in[3];
    const float* vc0  = (const float*)d_in[4];
    const float* vc1  = (const float*)d_in[5];
    const float* vc2  = (const float*)d_in[6];
    const float* b0   = (const float*)d_in[7];
    const float* b1   = (const float*)d_in[8];
    const float* b2   = (const float*)d_in[9];
    const float* fcw  = (const float*)d_in[10];
    const float* fcb  = (const float*)d_in[11];
    float* out = (float*)d_out;

    float *U, *h0, *h1, *hbar;
    __nv_bfloat16 *xh, *xl, *ah, *al, *bh, *bl, *wth, *wtl;
    cudaGetSymbolAddress((void**)&U,    g_U);
    cudaGetSymbolAddress((void**)&h0,   g_h0);
    cudaGetSymbolAddress((void**)&h1,   g_h1);
    cudaGetSymbolAddress((void**)&hbar, g_hbar);
    cudaGetSymbolAddress((void**)&xh,   g_xh);
    cudaGetSymbolAddress((void**)&xl,   g_xl);
    cudaGetSymbolAddress((void**)&ah,   g_ah);
    cudaGetSymbolAddress((void**)&al,   g_al);
    cudaGetSymbolAddress((void**)&bh,   g_bh);
    cudaGetSymbolAddress((void**)&bl,   g_bl);
    cudaGetSymbolAddress((void**)&wth,  g_wth);
    cudaGetSymbolAddress((void**)&wtl,  g_wtl);

    cudaFuncSetAttribute(gemm_bf16x3,
                         cudaFuncAttributeMaxDynamicSharedMemorySize, SMEM_GEMM);

    // split x once
    split_f32<<<(MROWS * IMG) / 256, 256>>>(x, xh, xl);

    // Layer 0: U = x @ W0  (M=24576, N=4096, K=512)
    wsplit_t<<<dim3(4096 / 32, IMG / 32), dim3(32, 8)>>>(W0, IMG, 4096, wth, wtl);
    gemm_bf16x3<<<dim3(4096 / 128, MROWS / 128), 256, SMEM_GEMM>>>(
        xh, xl, wth, wtl, U, IMG, 4096);
    sru_layer_kernel<true, true><<<B_SZ, HID>>>(U, 4096, nullptr, vc0, b0, h0, ah, al);

    // Layer 1: U = h0 @ W1 (N=3072, K=1024)
    wsplit_t<<<dim3(3072 / 32, HID / 32), dim3(32, 8)>>>(W1, HID, 3072, wth, wtl);
    gemm_bf16x3<<<dim3(3072 / 128, MROWS / 128), 256, SMEM_GEMM>>>(
        ah, al, wth, wtl, U, HID, 3072);
    sru_layer_kernel<false, true><<<B_SZ, HID>>>(U, 3072, h0, vc1, b1, h1, bh, bl);

    // Layer 2: U = h1 @ W2
    wsplit_t<<<dim3(3072 / 32, HID / 32), dim3(32, 8)>>>(W2, HID, 3072, wth, wtl);
    gemm_bf16x3<<<dim3(3072 / 128, MROWS / 128), 256, SMEM_GEMM>>>(
        bh, bl, wth, wtl, U, HID, 3072);
    sru_layer_kernel<false, false><<<B_SZ, HID>>>(U, 3072, h1, vc2, b2, h0,
                                                  nullptr, nullptr);

    // mean over t, then FC (mean commutes with the linear head)
    mean_kernel<<<(B_SZ * HID) / 256, 256>>>(h0, hbar);
    fc_kernel<<<B_SZ, 256>>>(hbar, fcw, fcb, out);
}

// round 13
// speedup vs baseline: 2.7790x; 1.0593x over previous
#include <cuda_runtime.h>
#include <cuda_bf16.h>
#include <math.h>
#include <stdint.h>

#define T_STEPS 12
#define HID     1024
#define B_SZ    2048
#define IMG     512
#define NCLS    51
#define MROWS   (T_STEPS * B_SZ)   /* 24576; row r = b*T + t */

#define SCALE_X 1.7320508075688772f  /* sqrt(3) */

// ---------------- scratch (device globals; no allocations allowed) ----------
__device__ __align__(256) float g_U [(size_t)MROWS * 4096];
__device__ __align__(256) float g_h0[(size_t)MROWS * HID];
__device__ __align__(256) float g_h1[(size_t)MROWS * HID];
__device__ __align__(256) float g_hbar[(size_t)B_SZ * HID];
// bf16 hi/lo splits of activations
__device__ __align__(256) __nv_bfloat16 g_xh[(size_t)MROWS * IMG];
__device__ __align__(256) __nv_bfloat16 g_xl[(size_t)MROWS * IMG];
__device__ __align__(256) __nv_bfloat16 g_ah[(size_t)MROWS * HID];
__device__ __align__(256) __nv_bfloat16 g_al[(size_t)MROWS * HID];
__device__ __align__(256) __nv_bfloat16 g_bh[(size_t)MROWS * HID];
__device__ __align__(256) __nv_bfloat16 g_bl[(size_t)MROWS * HID];
// bf16 splits of transposed weights [N][K] (max 4096x1024)
__device__ __align__(256) __nv_bfloat16 g_wth[(size_t)4096 * 1024];
__device__ __align__(256) __nv_bfloat16 g_wtl[(size_t)4096 * 1024];

// ======================= arch-neutral PTX helpers ===========================
__device__ __forceinline__ uint32_t smem_u32(const void* p) {
    uint32_t a;
    asm("{ .reg .u64 t; cvta.to.shared.u64 t, %1; cvt.u32.u64 %0, t; }"
        : "=r"(a) : "l"(p));
    return a;
}
__device__ __forceinline__ void cpa16(uint32_t dst, const void* src) {
    asm volatile("cp.async.cg.shared.global [%0], [%1], 16;"
                 :: "r"(dst), "l"(src) : "memory");
}
__device__ __forceinline__ void cpa_commit() {
    asm volatile("cp.async.commit_group;" ::: "memory");
}
__device__ __forceinline__ void cpa_wait1() {
    asm volatile("cp.async.wait_group 1;" ::: "memory");
}
__device__ __forceinline__ void ldsm4(uint32_t& r0, uint32_t& r1,
                                      uint32_t& r2, uint32_t& r3, uint32_t addr) {
    asm volatile("ldmatrix.sync.aligned.m8n8.x4.shared.b16 {%0,%1,%2,%3}, [%4];"
                 : "=r"(r0), "=r"(r1), "=r"(r2), "=r"(r3) : "r"(addr));
}
__device__ __forceinline__ void mma_bf16(float* c, const uint32_t* a,
                                         const uint32_t* b) {
    asm volatile(
        "mma.sync.aligned.m16n8k16.row.col.f32.bf16.bf16.f32 "
        "{%0,%1,%2,%3}, {%4,%5,%6,%7}, {%8,%9}, {%0,%1,%2,%3};"
        : "+f"(c[0]), "+f"(c[1]), "+f"(c[2]), "+f"(c[3])
        : "r"(a[0]), "r"(a[1]), "r"(a[2]), "r"(a[3]), "r"(b[0]), "r"(b[1]));
}

// ======================= bf16x3 tensor-core GEMM ============================
// C[M,N] (fp32) = Ah*Bh + Ah*Bl + Al*Bh (bf16 in, fp32 accumulate).
// A: [M,K] row-major; B: [N,K] row-major (pre-transposed -> mma row.col).
// CTA tile 128x256, BK=64 (128B rows, XOR swizzle), 8 warps of 64x64,
// 2-stage cp.async pipeline. grid = (N/256, M/128), 256 threads.
#define A_TILE     16384                    /* 128 rows x 128 B */
#define B_TILE     32768                    /* 256 rows x 128 B */
#define STAGE_BYTES (2 * A_TILE + 2 * B_TILE)   /* Ah, Al, Bh, Bl = 96 KB */
#define SMEM_GEMM  (2 * STAGE_BYTES)            /* 192 KB */

__global__ void __launch_bounds__(256)
gemm_bf16x3(const __nv_bfloat16* __restrict__ Ah, const __nv_bfloat16* __restrict__ Al,
            const __nv_bfloat16* __restrict__ Bh, const __nv_bfloat16* __restrict__ Bl,
            float* __restrict__ C, int K, int Nld)
{
    extern __shared__ char smem[];
    const uint32_t sb = smem_u32(smem);
    const int tid  = threadIdx.x;
    const int lane = tid & 31;
    const int wid  = tid >> 5;
    const int row0 = blockIdx.y * 128;
    const int col0 = blockIdx.x * 256;
    const int wm   = (wid >> 2) * 64;   // warp M offset (0 / 64)
    const int wn   = (wid & 3) * 64;    // warp N offset (0..192)

    const int NC = K >> 6;              // K/64 chunks

    float acc[4][8][4];
    #pragma unroll
    for (int i = 0; i < 4; ++i)
        #pragma unroll
        for (int j = 0; j < 8; ++j)
            #pragma unroll
            for (int q = 0; q < 4; ++q) acc[i][j][q] = 0.0f;

    // ---- stage fill: A 2x(128x8) + B 2x(256x8) 16B chunks; 24 cp.async/thread
    auto fill = [&](int ck) {
        const int k0 = ck << 6;
        const uint32_t stg = sb + (uint32_t)(ck & 1) * STAGE_BYTES;
        #pragma unroll
        for (int i = 0; i < 8; ++i) {            // A: 2048 chunks
            const int lin  = tid + i * 256;      // 0..2047
            const int tl   = lin >> 10;          // 0 = hi, 1 = lo
            const int r    = (lin >> 3) & 127;
            const int c    = lin & 7;
            const uint32_t so = (uint32_t)(r * 128 + ((c ^ (r & 7)) << 4));
            const size_t  go = (size_t)(row0 + r) * K + k0 + c * 8;
            cpa16(stg + (uint32_t)tl * A_TILE + so, (tl ? Al : Ah) + go);
        }
        #pragma unroll
        for (int i = 0; i < 16; ++i) {           // B: 4096 chunks
            const int lin  = tid + i * 256;      // 0..4095
            const int tl   = lin >> 11;          // 0 = hi, 1 = lo
            const int r    = (lin >> 3) & 255;
            const int c    = lin & 7;
            const uint32_t so = (uint32_t)(r * 128 + ((c ^ (r & 7)) << 4));
            const size_t  go = (size_t)(col0 + r) * K + k0 + c * 8;
            cpa16(stg + 2 * A_TILE + (uint32_t)tl * B_TILE + so, (tl ? Bl : Bh) + go);
        }
    };

    fill(0); cpa_commit();

    // lane-constant ldmatrix address components
    const int arow = wm + (lane & 15);               // A row within tile
    const int achi = lane >> 4;                      // A k-chunk hi bit
    const int brow = (lane & 7) + 8 * (lane >> 4);   // B row within 16-col group
    const int bchi = (lane >> 3) & 1;                // B k-chunk hi bit

    for (int ck = 0; ck < NC; ++ck) {
        if (ck + 1 < NC) fill(ck + 1);
        cpa_commit();                   // uniform group count (may be empty)
        cpa_wait1();                    // group for chunk ck complete
        __syncthreads();

        const uint32_t stg = sb + (uint32_t)(ck & 1) * STAGE_BYTES;
        const uint32_t sAh = stg, sAl = stg + A_TILE;
        const uint32_t sBh = stg + 2 * A_TILE, sBl = sBh + B_TILE;

        #pragma unroll
        for (int ks = 0; ks < 4; ++ks) {    // 4 x k16 per 64-chunk
            uint32_t fah[4][4], fal[4][4];
            #pragma unroll
            for (int mt = 0; mt < 4; ++mt) {
                const int r = arow + mt * 16;
                const int c = ks * 2 + achi;
                const uint32_t off = (uint32_t)(r * 128 + ((c ^ (r & 7)) << 4));
                ldsm4(fah[mt][0], fah[mt][1], fah[mt][2], fah[mt][3], sAh + off);
                ldsm4(fal[mt][0], fal[mt][1], fal[mt][2], fal[mt][3], sAl + off);
            }
            #pragma unroll
            for (int nb2 = 0; nb2 < 4; ++nb2) {   // 16 cols per block
                const int r = wn + nb2 * 16 + brow;
                const int c = ks * 2 + bchi;
                const uint32_t off = (uint32_t)(r * 128 + ((c ^ (r & 7)) << 4));
                uint32_t bh[2][2], bl[2][2];
                ldsm4(bh[0][0], bh[0][1], bh[1][0], bh[1][1], sBh + off);
                ldsm4(bl[0][0], bl[0][1], bl[1][0], bl[1][1], sBl + off);
                // term-major: consecutive mma never share an accumulator
                #pragma unroll
                for (int mt = 0; mt < 4; ++mt)
                    #pragma unroll
                    for (int nb = 0; nb < 2; ++nb)
                        mma_bf16(acc[mt][nb2 * 2 + nb], fah[mt], bh[nb]);
                #pragma unroll
                for (int mt = 0; mt < 4; ++mt)
                    #pragma unroll
                    for (int nb = 0; nb < 2; ++nb)
                        mma_bf16(acc[mt][nb2 * 2 + nb], fah[mt], bl[nb]);
                #pragma unroll
                for (int mt = 0; mt < 4; ++mt)
                    #pragma unroll
                    for (int nb = 0; nb < 2; ++nb)
                        mma_bf16(acc[mt][nb2 * 2 + nb], fal[mt], bh[nb]);
            }
        }
        __syncthreads();                // stage free before next fill
    }

    // ---- epilogue: direct fp32 stores (frag: rows g,g+8; cols 2i,2i+1)
    const int g  = lane >> 2;
    const int i2 = (lane & 3) * 2;
    #pragma unroll
    for (int mt = 0; mt < 4; ++mt) {
        #pragma unroll
        for (int nb = 0; nb < 8; ++nb) {
            const int row = row0 + wm + mt * 16 + g;
            const int col = col0 + wn + nb * 8 + i2;
            float* p  = C + (size_t)row * Nld + col;
            float* p2 = C + (size_t)(row + 8) * Nld + col;
            *(float2*)p  = make_float2(acc[mt][nb][0], acc[mt][nb][1]);
            *(float2*)p2 = make_float2(acc[mt][nb][2], acc[mt][nb][3]);
        }
    }
}

// ---------------- fp32 -> bf16 hi/lo split ----------------------------------
__global__ void split_f32(const float* __restrict__ a,
                          __nv_bfloat16* __restrict__ hi,
                          __nv_bfloat16* __restrict__ lo)
{
    const int i = blockIdx.x * blockDim.x + threadIdx.x;
    const float v = a[i];
    const __nv_bfloat16 h = __float2bfloat16(v);
    hi[i] = h;
    lo[i] = __float2bfloat16(v - __bfloat162float(h));
}

// ---------------- weight transpose + split: W[K,N] -> Wt_{h,l}[N,K] ---------
__global__ void __launch_bounds__(256)
wsplit_t(const float* __restrict__ W, int K, int N,
         __nv_bfloat16* __restrict__ Th, __nv_bfloat16* __restrict__ Tl)
{
    __shared__ float tile[32][33];
    const int n0 = blockIdx.x * 32, k0 = blockIdx.y * 32;
    const int tx = threadIdx.x, ty = threadIdx.y;   // (32, 8)
    #pragma unroll
    for (int r = 0; r < 4; ++r)
        tile[ty + 8 * r][tx] = W[(size_t)(k0 + ty + 8 * r) * N + n0 + tx];
    __syncthreads();
    #pragma unroll
    for (int r = 0; r < 4; ++r) {
        const int n = n0 + ty + 8 * r, k = k0 + tx;
        const float v = tile[tx][ty + 8 * r];
        const __nv_bfloat16 h = __float2bfloat16(v);
        Th[(size_t)n * K + k] = h;
        Tl[(size_t)n * K + k] = __float2bfloat16(v - __bfloat162float(h));
    }
}

// ---------------- SRU recurrence (optionally emits bf16 split of h) ---------
__device__ __forceinline__ float sigmoidf_(float x) {
    return 1.0f / (1.0f + expf(-x));
}

template <bool RESID_FROM_U, bool WRITE_SPLIT>
__global__ void __launch_bounds__(HID)
sru_layer_kernel(const float* __restrict__ U, int ustride,
                 const float* __restrict__ resid_h,
                 const float* __restrict__ vc, const float* __restrict__ bias,
                 float* __restrict__ h_out,
                 __nv_bfloat16* __restrict__ hh, __nv_bfloat16* __restrict__ hl)
{
    const int d = threadIdx.x;
    const int b = blockIdx.x;

    const float vf = vc[d],   vr = vc[HID + d];
    const float bf = bias[d], br = bias[HID + d];

    const float* Ub = U + (size_t)b * T_STEPS * ustride;
    const float* rb = RESID_FROM_U ? nullptr : (resid_h + (size_t)b * T_STEPS * HID);
    const size_t ob = (size_t)b * T_STEPS * HID;

    float c = 0.0f;
    #pragma unroll
    for (int t = 0; t < T_STEPS; ++t) {
        const float* Ut = Ub + (size_t)t * ustride;
        const float u0 = Ut[d];
        const float u1 = Ut[HID + d];
        const float u2 = Ut[2 * HID + d];
        const float xt = RESID_FROM_U ? Ut[3 * HID + d] : rb[(size_t)t * HID + d];

        const float f = sigmoidf_(u1 + vf * c + bf);
        c = f * c + (1.0f - f) * u0;
        const float r = sigmoidf_(u2 + vr * c + br);
        const float h = r * tanhf(c) + (1.0f - r) * xt * SCALE_X;
        const size_t o = ob + (size_t)t * HID + d;
        h_out[o] = h;
        if (WRITE_SPLIT) {
            const __nv_bfloat16 hi = __float2bfloat16(h);
            hh[o] = hi;
            hl[o] = __float2bfloat16(h - __bfloat162float(hi));
        }
    }
}

// ---- final SRU layer fused with the t-mean: only hbar is materialized ------
__global__ void __launch_bounds__(HID)
sru_layer_mean_kernel(const float* __restrict__ U, int ustride,
                      const float* __restrict__ resid_h,
                      const float* __restrict__ vc, const float* __restrict__ bias,
                      float* __restrict__ hbar)
{
    const int d = threadIdx.x;
    const int b = blockIdx.x;

    const float vf = vc[d],   vr = vc[HID + d];
    const float bf = bias[d], br = bias[HID + d];

    const float* Ub = U + (size_t)b * T_STEPS * ustride;
    const float* rb = resid_h + (size_t)b * T_STEPS * HID;

    float c = 0.0f, s = 0.0f;
    #pragma unroll
    for (int t = 0; t < T_STEPS; ++t) {
        const float* Ut = Ub + (size_t)t * ustride;
        const float u0 = Ut[d];
        const float u1 = Ut[HID + d];
        const float u2 = Ut[2 * HID + d];
        const float xt = rb[(size_t)t * HID + d];

        const float f = sigmoidf_(u1 + vf * c + bf);
        c = f * c + (1.0f - f) * u0;
        const float r = sigmoidf_(u2 + vr * c + br);
        s += r * tanhf(c) + (1.0f - r) * xt * SCALE_X;
    }
    hbar[(size_t)b * HID + d] = s * (1.0f / T_STEPS);
}

// ---------------- FC head ----------------------------------------------------
__global__ void __launch_bounds__(256)
fc_kernel(const float* __restrict__ hbar, const float* __restrict__ w,
          const float* __restrict__ bias, float* __restrict__ out)
{
    __shared__ float hrow[HID];
    __shared__ float part[4][64];
    const int b   = blockIdx.x;
    const int tid = threadIdx.x;

    #pragma unroll
    for (int i = tid; i < HID; i += 256) hrow[i] = hbar[(size_t)b * HID + i];
    __syncthreads();

    const int c  = tid & 63;
    const int sl = tid >> 6;
    float s = 0.0f;
    if (c < NCLS) {
        const int d0 = sl * 256;
        #pragma unroll 8
        for (int d = d0; d < d0 + 256; ++d)
            s = fmaf(hrow[d], w[(size_t)d * NCLS + c], s);
    }
    part[sl][c] = s;
    __syncthreads();

    if (tid < NCLS)
        out[(size_t)b * NCLS + tid] =
            part[0][tid] + part[1][tid] + part[2][tid] + part[3][tid] + bias[tid];
}

// ---------------- launch -----------------------------------------------------
extern "C" void kernel_launch(void* const* d_in, const int* in_sizes, int n_in,
                              void* d_out, int out_size)
{
    const float* x    = (const float*)d_in[0];
    const float* W0   = (const float*)d_in[1];
    const float* W1   = (const float*)d_in[2];
    const float* W2   = (const float*)d_in[3];
    const float* vc0  = (const float*)d_in[4];
    const float* vc1  = (const float*)d_in[5];
    const float* vc2  = (const float*)d_in[6];
    const float* b0   = (const float*)d_in[7];
    const float* b1   = (const float*)d_in[8];
    const float* b2   = (const float*)d_in[9];
    const float* fcw  = (const float*)d_in[10];
    const float* fcb  = (const float*)d_in[11];
    float* out = (float*)d_out;

    float *U, *h0, *h1, *hbar;
    __nv_bfloat16 *xh, *xl, *ah, *al, *bh, *bl, *wth, *wtl;
    cudaGetSymbolAddress((void**)&U,    g_U);
    cudaGetSymbolAddress((void**)&h0,   g_h0);
    cudaGetSymbolAddress((void**)&h1,   g_h1);
    cudaGetSymbolAddress((void**)&hbar, g_hbar);
    cudaGetSymbolAddress((void**)&xh,   g_xh);
    cudaGetSymbolAddress((void**)&xl,   g_xl);
    cudaGetSymbolAddress((void**)&ah,   g_ah);
    cudaGetSymbolAddress((void**)&al,   g_al);
    cudaGetSymbolAddress((void**)&bh,   g_bh);
    cudaGetSymbolAddress((void**)&bl,   g_bl);
    cudaGetSymbolAddress((void**)&wth,  g_wth);
    cudaGetSymbolAddress((void**)&wtl,  g_wtl);

    cudaFuncSetAttribute(gemm_bf16x3,
                         cudaFuncAttributeMaxDynamicSharedMemorySize, SMEM_GEMM);

    // split x once
    split_f32<<<(MROWS * IMG) / 256, 256>>>(x, xh, xl);

    // Layer 0: U = x @ W0  (M=24576, N=4096, K=512)
    wsplit_t<<<dim3(4096 / 32, IMG / 32), dim3(32, 8)>>>(W0, IMG, 4096, wth, wtl);
    gemm_bf16x3<<<dim3(4096 / 256, MROWS / 128), 256, SMEM_GEMM>>>(
        xh, xl, wth, wtl, U, IMG, 4096);
    sru_layer_kernel<true, true><<<B_SZ, HID>>>(U, 4096, nullptr, vc0, b0, h0, ah, al);

    // Layer 1: U = h0 @ W1 (N=3072, K=1024)
    wsplit_t<<<dim3(3072 / 32, HID / 32), dim3(32, 8)>>>(W1, HID, 3072, wth, wtl);
    gemm_bf16x3<<<dim3(3072 / 256, MROWS / 128), 256, SMEM_GEMM>>>(
        ah, al, wth, wtl, U, HID, 3072);
    sru_layer_kernel<false, true><<<B_SZ, HID>>>(U, 3072, h0, vc1, b1, h1, bh, bl);

    // Layer 2: U = h1 @ W2; fuse recurrence + mean (h never materialized)
    wsplit_t<<<dim3(3072 / 32, HID / 32), dim3(32, 8)>>>(W2, HID, 3072, wth, wtl);
    gemm_bf16x3<<<dim3(3072 / 256, MROWS / 128), 256, SMEM_GEMM>>>(
        bh, bl, wth, wtl, U, HID, 3072);
    sru_layer_mean_kernel<<<B_SZ, HID>>>(U, 3072, h1, vc2, b2, hbar);

    // FC head on time-averaged h (mean commutes with the linear head)
    fc_kernel<<<B_SZ, 256>>>(hbar, fcw, fcb, out);
}